// round 16
// baseline (speedup 1.0000x reference)
#include <cuda_runtime.h>
#include <cuda_fp16.h>
#include <cstdint>

// ---------------------------------------------------------------------------
// CTDExplainer: 3-layer relational GCN explainer. N=8192, D=64, R=3, E=262144.
// Round 16: edge aggregation atomics eliminated — a row-CSR (histogram +
// scan + scatter over the static edge_row input) is built once per call on
// the side stream (hidden under layer-0 zgemm); edge_csr then gives each
// warp exclusive ownership of one destination row: register accumulation,
// coalesced HW gather, single non-atomic RMW. ngemm/zgemm identical to r15.
// Output layout: [ H (N*64) | z0 (N*N) | z1 | z2 ]  fp32.
// ---------------------------------------------------------------------------

#define MAXN 8192
#define MAXE 262144
#define D 64

__device__ float g_HW  [3 * MAXN * D];
__device__ float g_aggA[MAXN * D];
__device__ float g_aggB[MAXN * D];
__device__ uint2 g_hbhi[MAXN * D / 4];
__device__ uint2 g_hblo[MAXN * D / 4];
__device__ uint2 g_hhi [MAXN * D / 4];
__device__ int   g_cnt [MAXN];
__device__ int   g_off [MAXN + 1];
__device__ int   g_perm[MAXE];

__device__ __forceinline__ uint32_t smem_u32(const void* p) {
    uint32_t a;
    asm("{ .reg .u64 t; cvta.to.shared.u64 t, %1; cvt.u32.u64 %0, t; }" : "=r"(a) : "l"(p));
    return a;
}
__device__ __forceinline__ void ldm_x4(uint32_t& r0, uint32_t& r1, uint32_t& r2,
                                       uint32_t& r3, uint32_t addr) {
    asm volatile("ldmatrix.sync.aligned.m8n8.x4.shared.b16 {%0,%1,%2,%3}, [%4];"
                 : "=r"(r0), "=r"(r1), "=r"(r2), "=r"(r3) : "r"(addr));
}
__device__ __forceinline__ void mma16816(float* c, const uint32_t* a,
                                         uint32_t b0, uint32_t b1) {
    asm volatile(
        "mma.sync.aligned.m16n8k16.row.col.f32.f16.f16.f32 "
        "{%0,%1,%2,%3}, {%4,%5,%6,%7}, {%8,%9}, {%0,%1,%2,%3};"
        : "+f"(c[0]), "+f"(c[1]), "+f"(c[2]), "+f"(c[3])
        : "r"(a[0]), "r"(a[1]), "r"(a[2]), "r"(a[3]), "r"(b0), "r"(b1));
}
__device__ __forceinline__ void cpa16(uint32_t saddr, const void* gaddr) {
    asm volatile("cp.async.cg.shared.global [%0], [%1], 16;"
                 :: "r"(saddr), "l"(gaddr));
}

// ---------------- CSR build (once per call, side stream) --------------------
__global__ void csr_zero(int* cnt, int n) {
    int i = blockIdx.x * blockDim.x + threadIdx.x;
    if (i < n) cnt[i] = 0;
}
__global__ void csr_hist(const int* __restrict__ row, int* cnt, int E) {
    int e = blockIdx.x * blockDim.x + threadIdx.x;
    if (e < E) atomicAdd(&cnt[row[e]], 1);
}
// single block, 1024 threads, n = 8192 (= 1024*8)
__global__ void csr_scan(const int* __restrict__ cnt, int* __restrict__ off, int n) {
    __shared__ int part[1024];
    const int t = threadIdx.x;
    int local[8];
    int sum = 0;
#pragma unroll
    for (int j = 0; j < 8; j++) {
        local[j] = sum;
        sum += cnt[t * 8 + j];
    }
    part[t] = sum;
    __syncthreads();
    for (int d = 1; d < 1024; d <<= 1) {
        int v = (t >= d) ? part[t - d] : 0;
        __syncthreads();
        part[t] += v;
        __syncthreads();
    }
    int base = (t == 0) ? 0 : part[t - 1];
#pragma unroll
    for (int j = 0; j < 8; j++) off[t * 8 + j] = base + local[j];
    if (t == 1023) off[n] = part[1023];
}
__global__ void csr_scatter(const int* __restrict__ row, const int* __restrict__ off,
                            int* cur, int* __restrict__ perm, int E) {
    int e = blockIdx.x * blockDim.x + threadIdx.x;
    if (e >= E) return;
    int r = row[e];
    int pos = off[r] + atomicAdd(&cur[r], 1);
    perm[pos] = e;
}

// ---------------- HMMA per-layer small GEMMs (LN/relu/concat fused) ---------
#define NG_IHI 0
#define NG_ILO 8192
#define NG_WHI 16384
#define NG_WLO 24576
#define NG_TOT 32768

__global__ void __launch_bounds__(128, 4) ngemm_mma(
    const float* __restrict__ inA, const float* __restrict__ inB, int nxrows,
    const float* __restrict__ lng, const float* __restrict__ lnb,
    const float* __restrict__ bilin, const float* __restrict__ Wrel,
    const float* __restrict__ Wroot, const float* __restrict__ bias,
    __half2* __restrict__ hbhi, __half2* __restrict__ hblo,
    __half2* __restrict__ hhi, float* __restrict__ HW,
    float* __restrict__ agg, int relu, int N, int obase) {
    extern __shared__ __align__(16) char smem[];
    const int tid  = threadIdx.x;
    const int row0 = blockIdx.x * 64;
    const int o    = blockIdx.y + obase;
    const uint32_t sb = smem_u32(smem);

    const float* W = (o == 0) ? bilin : (o < 4) ? Wrel + (size_t)(o - 1) * 4096 : Wroot;
    const int act = (o > 0) ? relu : 0;

    const int r    = tid >> 1;
    const int hlf  = tid & 1;
    const int gr   = row0 + r;
    const float* src = (inB && gr >= nxrows)
                     ? (inB + (size_t)(gr - nxrows) * 64 + hlf * 32)
                     : (inA + (size_t)gr * 64 + hlf * 32);
    float v[32];
#pragma unroll
    for (int i = 0; i < 8; i++) {
        float4 t = *(const float4*)(src + i * 4);
        v[i*4+0] = t.x; v[i*4+1] = t.y; v[i*4+2] = t.z; v[i*4+3] = t.w;
    }
    float wv[32];
#pragma unroll
    for (int it = 0; it < 8; it++) {
        const int q  = tid + it * 128;
        const int k0 = (q >> 6) << 2;
        const int n  = q & 63;
#pragma unroll
        for (int j = 0; j < 4; j++)
            wv[it * 4 + j] = __ldg(W + (k0 + j) * 64 + n);
    }

    {
        if (lng) {
            float s = 0.f, q = 0.f;
#pragma unroll
            for (int i = 0; i < 32; i++) { s += v[i]; q += v[i] * v[i]; }
            s += __shfl_xor_sync(0xffffffffu, s, 1);
            q += __shfl_xor_sync(0xffffffffu, q, 1);
            float mu  = s * (1.f / 64.f);
            float inv = rsqrtf(q * (1.f / 64.f) - mu * mu + 1e-5f);
#pragma unroll
            for (int i = 0; i < 32; i++) {
                int c = hlf * 32 + i;
                v[i] = (v[i] - mu) * inv * lng[c] + lnb[c];
            }
        }
        if (o == 0) {
            __half2* dst = hhi + ((size_t)gr * 64 + hlf * 32) / 2;
#pragma unroll
            for (int i = 0; i < 16; i++)
                dst[i] = __halves2half2(__float2half_rn(v[2*i]),
                                        __float2half_rn(v[2*i+1]));
        } else if (act) {
#pragma unroll
            for (int i = 0; i < 32; i++) v[i] = fmaxf(v[i], 0.f);
        }
        const int r7 = r & 7;
#pragma unroll
        for (int u = 0; u < 4; u++) {
            __half hs[8], ls[8];
#pragma unroll
            for (int j = 0; j < 8; j++) {
                float x = v[u * 8 + j];
                __half h = __float2half_rn(x);
                hs[j] = h;
                ls[j] = __float2half_rn(x - __half2float(h));
            }
            uint32_t unit = (uint32_t)(hlf * 4 + u) ^ (uint32_t)r7;
            uint32_t byte = r * 128 + unit * 16;
            *(uint4*)(smem + NG_IHI + byte) = *(uint4*)hs;
            *(uint4*)(smem + NG_ILO + byte) = *(uint4*)ls;
        }
    }

#pragma unroll
    for (int it = 0; it < 8; it++) {
        const int q  = tid + it * 128;
        const int k0 = (q >> 6) << 2;
        const int n  = q & 63;
        __half hs[4], ls[4];
#pragma unroll
        for (int j = 0; j < 4; j++) {
            float w = wv[it * 4 + j];
            __half h = __float2half_rn(w);
            hs[j] = h;
            ls[j] = __float2half_rn(w - __half2float(h));
        }
        uint32_t unit = (uint32_t)(k0 >> 3) ^ (uint32_t)(n & 7);
        uint32_t byte = n * 128 + unit * 16 + (k0 & 7) * 2;
        *(uint2*)(smem + NG_WHI + byte) = *(uint2*)hs;
        *(uint2*)(smem + NG_WLO + byte) = *(uint2*)ls;
    }
    __syncthreads();

    const int lane = tid & 31;
    const int wid  = tid >> 5;
    const int wm   = wid * 16;
    const int a_row = wm + (lane & 15);
    const int a_r7  = a_row & 7;
    const int au    = lane >> 4;
    const int b_row = (lane & 7) + (((lane >> 4) & 1) << 3);
    const int b_r7  = b_row & 7;
    const int bu    = (lane >> 3) & 1;

    const uint32_t ahib = sb + NG_IHI + a_row * 128;
    const uint32_t alob = sb + NG_ILO + a_row * 128;
    const uint32_t whib = sb + NG_WHI + b_row * 128;
    const uint32_t wlob = sb + NG_WLO + b_row * 128;

    float acc[8][4];
#pragma unroll
    for (int i = 0; i < 8; i++)
#pragma unroll
        for (int j = 0; j < 4; j++) acc[i][j] = 0.f;

#pragma unroll
    for (int kc = 0; kc < 4; kc++) {
        const uint32_t aoff = ((((kc << 1) + au) ^ a_r7) << 4);
        const uint32_t boff = ((((kc << 1) + bu) ^ b_r7) << 4);
        uint32_t Ah[4], Al[4];
        ldm_x4(Ah[0], Ah[1], Ah[2], Ah[3], ahib + aoff);
        ldm_x4(Al[0], Al[1], Al[2], Al[3], alob + aoff);
#pragma unroll
        for (int nt = 0; nt < 4; nt++) {
            uint32_t bh[4], bl[4];
            ldm_x4(bh[0], bh[1], bh[2], bh[3], whib + boff + nt * 16 * 128);
            ldm_x4(bl[0], bl[1], bl[2], bl[3], wlob + boff + nt * 16 * 128);
            float* a0 = acc[2 * nt];
            float* a1 = acc[2 * nt + 1];
            mma16816(a0, Ah, bh[0], bh[1]);
            mma16816(a1, Ah, bh[2], bh[3]);
            mma16816(a0, Al, bh[0], bh[1]);
            mma16816(a1, Al, bh[2], bh[3]);
            mma16816(a0, Ah, bl[0], bl[1]);
            mma16816(a1, Ah, bl[2], bl[3]);
        }
    }

    const int er = lane >> 2;
    const int ec = (lane & 3) * 2;
    const int gro = row0 + wm + er;
    if (o == 0) {
#pragma unroll
        for (int ni = 0; ni < 8; ni++) {
            float* f = acc[ni];
            int col = ni * 8 + ec;
            size_t i0 = ((size_t)gro * 64 + col) / 2;
            size_t i1 = ((size_t)(gro + 8) * 64 + col) / 2;
            __half h0 = __float2half_rn(f[0]), h1 = __float2half_rn(f[1]);
            __half h2 = __float2half_rn(f[2]), h3 = __float2half_rn(f[3]);
            hbhi[i0] = __halves2half2(h0, h1);
            hbhi[i1] = __halves2half2(h2, h3);
            hblo[i0] = __halves2half2(__float2half_rn(f[0] - __half2float(h0)),
                                      __float2half_rn(f[1] - __half2float(h1)));
            hblo[i1] = __halves2half2(__float2half_rn(f[2] - __half2float(h2)),
                                      __float2half_rn(f[3] - __half2float(h3)));
        }
    } else if (o < 4) {
        float* Out = HW + (size_t)(o - 1) * N * 64;
#pragma unroll
        for (int ni = 0; ni < 8; ni++) {
            float* f = acc[ni];
            int col = ni * 8 + ec;
            *(float2*)(Out + (size_t)gro * 64 + col)       = make_float2(f[0], f[1]);
            *(float2*)(Out + (size_t)(gro + 8) * 64 + col) = make_float2(f[2], f[3]);
        }
    } else {
#pragma unroll
        for (int ni = 0; ni < 8; ni++) {
            float* f = acc[ni];
            int col = ni * 8 + ec;
            float b0 = bias[col], b1 = bias[col + 1];
            *(float2*)(agg + (size_t)gro * 64 + col)       = make_float2(f[0] + b0, f[1] + b1);
            *(float2*)(agg + (size_t)(gro + 8) * 64 + col) = make_float2(f[2] + b0, f[3] + b1);
        }
    }
}

// ---------------- persistent HMMA GEMM: C = (Ahi + Alo) @ Bhi^T -------------
#define TILEB 16384
#define SM_TOT (4 * TILEB)

__global__ void __launch_bounds__(256, 2) zgemm_mma(
    const __half* __restrict__ Ahi, const __half* __restrict__ Alo,
    const __half* __restrict__ Bhi, float* __restrict__ C, int N,
    int total_tiles) {
    extern __shared__ __align__(16) char smem[];
    const int tid = threadIdx.x;
    const uint32_t sb = smem_u32(smem);

    const int lrow = tid >> 1;
    const int lcu  = (tid & 1) * 4;
    const int lr7  = lrow & 7;
    const int lcol = (tid & 1) * 32;
    uint32_t soff[4];
#pragma unroll
    for (int i = 0; i < 4; i++)
        soff[i] = lrow * 128 + (((lcu + i) ^ lr7) << 4);

    auto loadA = [&](int band) {
        const __half* gA0 = Ahi + (size_t)(band * 128 + lrow) * 64 + lcol;
        const __half* gA1 = Alo + (size_t)(band * 128 + lrow) * 64 + lcol;
#pragma unroll
        for (int i = 0; i < 4; i++) {
            cpa16(sb + 0 * TILEB + soff[i], gA0 + i * 8);
            cpa16(sb + 1 * TILEB + soff[i], gA1 + i * 8);
        }
    };
    auto issueB = [&](int buf, int n0) {
        const __half* gB = Bhi + (size_t)(n0 * 128 + lrow) * 64 + lcol;
        const uint32_t s0 = sb + 2 * TILEB + buf * TILEB;
#pragma unroll
        for (int i = 0; i < 4; i++)
            cpa16(s0 + soff[i], gB + i * 8);
    };

    const int lane = tid & 31;
    const int wid  = tid >> 5;
    const int wm   = (wid & 3) * 32;
    const int wn   = (wid >> 2) * 64;

    const int a_row = wm + (lane & 15);
    const int a_r7  = a_row & 7;
    const int au    = lane >> 4;
    const int b_row = wn + (lane & 7) + (((lane >> 4) & 1) << 3);
    const int b_r7  = b_row & 7;
    const int bu    = (lane >> 3) & 1;
    const int er = lane >> 2;
    const int ec = (lane & 3) * 2;

    uint32_t aoffk[4], boffk[4];
#pragma unroll
    for (int kc = 0; kc < 4; kc++) {
        aoffk[kc] = ((((kc << 1) + au) ^ a_r7) << 4);
        boffk[kc] = ((((kc << 1) + bu) ^ b_r7) << 4);
    }
    const uint32_t abase_row = sb + a_row * 128;
    const uint32_t bbase0    = sb + 2 * TILEB + b_row * 128;

    const int G = gridDim.x;
    const int p = blockIdx.x;
    const int start = (int)(((long long)p * total_tiles) / G);
    const int end   = (int)(((long long)(p + 1) * total_tiles) / G);
    if (start >= end) return;

    int curBand = start >> 6;
    loadA(curBand);
    issueB(0, start & 63);
    asm volatile("cp.async.commit_group;");

    int idx = 0;
    for (int t = start; t < end; t++, idx++) {
        const int band = t >> 6;
        if (band != curBand) {
            loadA(band);
            asm volatile("cp.async.commit_group;");
            curBand = band;
        }
        const int buf = idx & 1;
        if (t + 1 < end) issueB(1 - buf, (t + 1) & 63);
        asm volatile("cp.async.commit_group;");
        asm volatile("cp.async.wait_group 1;");
        __syncthreads();

        const uint32_t bbase_row = bbase0 + (buf ? (uint32_t)TILEB : 0u);

        float acc[16][4];
#pragma unroll
        for (int i = 0; i < 16; i++)
#pragma unroll
            for (int j = 0; j < 4; j++) acc[i][j] = 0.f;

#pragma unroll
        for (int kc = 0; kc < 4; kc++) {
            uint32_t Ah[8], Al[8], bh[16];
            ldm_x4(Ah[0], Ah[1], Ah[2], Ah[3], abase_row + aoffk[kc]);
            ldm_x4(Ah[4], Ah[5], Ah[6], Ah[7], abase_row + aoffk[kc] + 16 * 128);
            ldm_x4(Al[0], Al[1], Al[2], Al[3], abase_row + TILEB + aoffk[kc]);
            ldm_x4(Al[4], Al[5], Al[6], Al[7], abase_row + TILEB + aoffk[kc] + 16 * 128);
#pragma unroll
            for (int nt2 = 0; nt2 < 4; nt2++)
                ldm_x4(bh[4 * nt2], bh[4 * nt2 + 1], bh[4 * nt2 + 2], bh[4 * nt2 + 3],
                       bbase_row + boffk[kc] + nt2 * 16 * 128);
#pragma unroll
            for (int nt2 = 0; nt2 < 4; nt2++) {
                mma16816(acc[2 * nt2],         Ah,     bh[4 * nt2],     bh[4 * nt2 + 1]);
                mma16816(acc[2 * nt2 + 1],     Ah,     bh[4 * nt2 + 2], bh[4 * nt2 + 3]);
                mma16816(acc[8 + 2 * nt2],     Ah + 4, bh[4 * nt2],     bh[4 * nt2 + 1]);
                mma16816(acc[8 + 2 * nt2 + 1], Ah + 4, bh[4 * nt2 + 2], bh[4 * nt2 + 3]);
            }
#pragma unroll
            for (int nt2 = 0; nt2 < 4; nt2++) {
                mma16816(acc[2 * nt2],         Al,     bh[4 * nt2],     bh[4 * nt2 + 1]);
                mma16816(acc[2 * nt2 + 1],     Al,     bh[4 * nt2 + 2], bh[4 * nt2 + 3]);
                mma16816(acc[8 + 2 * nt2],     Al + 4, bh[4 * nt2],     bh[4 * nt2 + 1]);
                mma16816(acc[8 + 2 * nt2 + 1], Al + 4, bh[4 * nt2 + 2], bh[4 * nt2 + 3]);
            }
        }

        const int m0 = band * 128;
        const int n0 = (t & 63) * 128;
#pragma unroll
        for (int mi = 0; mi < 2; mi++)
#pragma unroll
            for (int ni = 0; ni < 8; ni++) {
                float* f = acc[mi * 8 + ni];
                size_t rr = (size_t)(m0 + wm + mi * 16 + er);
                int col = n0 + wn + ni * 8 + ec;
                *(float2*)(C + rr * N + col)       = make_float2(f[0], f[1]);
                *(float2*)(C + (rr + 8) * N + col) = make_float2(f[2], f[3]);
            }
        __syncthreads();
    }
}

// ---------------- edge aggregation: one warp per destination row (CSR) ------
// agg[r] += sum_{e in row r} HW[etype[e], col[e]] * Z[r, col[e]] * ev[e]
// No atomics: warp owns its row exclusively.
__global__ void edge_csr(const float* __restrict__ Z, const float* __restrict__ HW,
                         const int* __restrict__ col, const int* __restrict__ et,
                         const float* __restrict__ ev, const int* __restrict__ off,
                         const int* __restrict__ perm, float* __restrict__ agg, int N) {
    int w    = (blockIdx.x * blockDim.x + threadIdx.x) >> 5;
    int lane = threadIdx.x & 31;
    if (w >= N) return;
    int s  = off[w];
    int en = off[w + 1];
    if (s == en) return;
    const float* Zr = Z + (size_t)w * N;
    float2 acc = make_float2(0.f, 0.f);
    int i = s;
    for (; i + 1 < en; i += 2) {
        int ea = perm[i], eb = perm[i + 1];
        int ca = col[ea], cb = col[eb];
        int ta = et[ea],  tb = et[eb];
        float aa = Zr[ca] * ev[ea];
        float ab = Zr[cb] * ev[eb];
        float2 ma = ((const float2*)(HW + ((size_t)ta * N + ca) * 64))[lane];
        float2 mb = ((const float2*)(HW + ((size_t)tb * N + cb) * 64))[lane];
        acc.x += ma.x * aa; acc.y += ma.y * aa;
        acc.x += mb.x * ab; acc.y += mb.y * ab;
    }
    if (i < en) {
        int ea = perm[i];
        int ca = col[ea];
        float aa = Zr[ca] * ev[ea];
        float2 ma = ((const float2*)(HW + ((size_t)et[ea] * N + ca) * 64))[lane];
        acc.x += ma.x * aa; acc.y += ma.y * aa;
    }
    float2* dst = (float2*)(agg + (size_t)w * 64) + lane;
    float2 d = *dst;
    d.x += acc.x; d.y += acc.y;
    *dst = d;
}

// ---------------------------------------------------------------------------
extern "C" void kernel_launch(void* const* d_in, const int* in_sizes, int n_in,
                              void* d_out, int out_size) {
    const float* x       = (const float*)d_in[0];
    const float* emb     = (const float*)d_in[1];
    const float* bilin   = (const float*)d_in[2];
    const float* eval    = (const float*)d_in[3];
    const float* W_root  = (const float*)d_in[4];
    const float* W_rel   = (const float*)d_in[5];
    const float* bias    = (const float*)d_in[6];
    const float* ln_g    = (const float*)d_in[7];
    const float* ln_b    = (const float*)d_in[8];
    const int*   erow    = (const int*)d_in[9];
    const int*   ecol    = (const int*)d_in[10];
    const int*   etype   = (const int*)d_in[11];

    const int NX = in_sizes[0] / D;
    const int NE = in_sizes[1] / D;
    const int N  = NX + NE;
    const int E  = in_sizes[3];

    float* out   = (float*)d_out;
    float* Hout  = out;
    float* Zbase = out + (size_t)N * D;

    float *HW, *aggA, *aggB;
    uint2 *hbhi, *hblo, *hhi;
    int *cnt, *off, *perm;
    cudaGetSymbolAddress((void**)&HW,   g_HW);
    cudaGetSymbolAddress((void**)&aggA, g_aggA);
    cudaGetSymbolAddress((void**)&aggB, g_aggB);
    cudaGetSymbolAddress((void**)&hbhi, g_hbhi);
    cudaGetSymbolAddress((void**)&hblo, g_hblo);
    cudaGetSymbolAddress((void**)&hhi,  g_hhi);
    cudaGetSymbolAddress((void**)&cnt,  g_cnt);
    cudaGetSymbolAddress((void**)&off,  g_off);
    cudaGetSymbolAddress((void**)&perm, g_perm);

    cudaFuncSetAttribute(zgemm_mma, cudaFuncAttributeMaxDynamicSharedMemorySize, SM_TOT);
    cudaFuncSetAttribute(ngemm_mma, cudaFuncAttributeMaxDynamicSharedMemorySize, NG_TOT);

    static cudaStream_t s2 = nullptr;
    static cudaEvent_t evFork = nullptr, evRest = nullptr;
    if (!s2) {
        cudaStreamCreateWithFlags(&s2, cudaStreamNonBlocking);
        cudaEventCreateWithFlags(&evFork, cudaEventDisableTiming);
        cudaEventCreateWithFlags(&evRest, cudaEventDisableTiming);
    }

    int nsm = 148;
    cudaDeviceGetAttribute(&nsm, cudaDevAttrMultiProcessorCount, 0);

    const int tiles_n = N / 128;
    const int total_tiles = tiles_n * tiles_n;
    const int zgrid = 2 * nsm;
    const int edge_blocks = (N * 32 + 255) / 256;

    // CSR build on side stream — hidden under layer-0 ngemm/zgemm; edge(0)
    // waits on evRest which is recorded after these on s2.
    csr_zero<<<(N + 255) / 256, 256, 0, s2>>>(cnt, N);
    csr_hist<<<(E + 255) / 256, 256, 0, s2>>>(erow, cnt, E);
    csr_scan<<<1, 1024, 0, s2>>>(cnt, off, N);
    csr_zero<<<(N + 255) / 256, 256, 0, s2>>>(cnt, N);
    csr_scatter<<<(E + 255) / 256, 256, 0, s2>>>(erow, off, cnt, perm, E);

    const float* insA[3] = { x, aggA, aggB };
    const float* insB[3] = { emb, nullptr, nullptr };
    float*       outs[3] = { aggA, aggB, Hout };

    for (int l = 0; l < 3; l++) {
        float* Zl   = Zbase + (size_t)l * N * N;
        const float* lng = (l == 0) ? nullptr : ln_g + (size_t)(l - 1) * D;
        const float* lnb = (l == 0) ? nullptr : ln_b + (size_t)(l - 1) * D;
        int relu = (l > 0) ? 1 : 0;

        // fork: HW + agg (o=1..4) on s2, overlapping o=0 + zgemm on main
        cudaEventRecord(evFork, 0);
        cudaStreamWaitEvent(s2, evFork, 0);
        ngemm_mma<<<dim3(N / 64, 4), 128, NG_TOT, s2>>>(
            insA[l], insB[l], NX, lng, lnb,
            bilin + (size_t)l * D * D, W_rel + (size_t)l * 3 * D * D,
            W_root + (size_t)l * D * D, bias + (size_t)l * D,
            (__half2*)hbhi, (__half2*)hblo, (__half2*)hhi,
            HW, outs[l], relu, N, /*obase=*/1);
        cudaEventRecord(evRest, s2);

        ngemm_mma<<<dim3(N / 64, 1), 128, NG_TOT>>>(
            insA[l], insB[l], NX, lng, lnb,
            bilin + (size_t)l * D * D, W_rel + (size_t)l * 3 * D * D,
            W_root + (size_t)l * D * D, bias + (size_t)l * D,
            (__half2*)hbhi, (__half2*)hblo, (__half2*)hhi,
            HW, outs[l], relu, N, /*obase=*/0);
        zgemm_mma<<<zgrid, 256, SM_TOT>>>((const __half*)hbhi, (const __half*)hblo,
                                          (const __half*)hhi, Zl, N, total_tiles);

        // join: edge needs Z, HW, agg (and CSR, ordered before rest on s2)
        cudaStreamWaitEvent(0, evRest, 0);
        edge_csr<<<edge_blocks, 256>>>(Zl, HW, ecol, etype, eval, off, perm,
                                       outs[l], N);
    }
}

// round 17
// speedup vs baseline: 1.0796x; 1.0796x over previous
#include <cuda_runtime.h>
#include <cuda_fp16.h>
#include <cstdint>

// ---------------------------------------------------------------------------
// CTDExplainer: 3-layer relational GCN explainer. N=8192, D=64, R=3, E=262144.
// Round 17: edge_csr rewritten with 8-way ILP (batch index loads, 8 parallel
// Z + HW gathers per chunk -> MLP~16, kills the r16 serial pointer-chase).
// CSR build / ngemm / zgemm identical to r16 (r15 for the compute kernels).
// Output layout: [ H (N*64) | z0 (N*N) | z1 | z2 ]  fp32.
// ---------------------------------------------------------------------------

#define MAXN 8192
#define MAXE 262144
#define D 64

__device__ float g_HW  [3 * MAXN * D];
__device__ float g_aggA[MAXN * D];
__device__ float g_aggB[MAXN * D];
__device__ uint2 g_hbhi[MAXN * D / 4];
__device__ uint2 g_hblo[MAXN * D / 4];
__device__ uint2 g_hhi [MAXN * D / 4];
__device__ int   g_cnt [MAXN];
__device__ int   g_off [MAXN + 1];
__device__ int   g_perm[MAXE];

__device__ __forceinline__ uint32_t smem_u32(const void* p) {
    uint32_t a;
    asm("{ .reg .u64 t; cvta.to.shared.u64 t, %1; cvt.u32.u64 %0, t; }" : "=r"(a) : "l"(p));
    return a;
}
__device__ __forceinline__ void ldm_x4(uint32_t& r0, uint32_t& r1, uint32_t& r2,
                                       uint32_t& r3, uint32_t addr) {
    asm volatile("ldmatrix.sync.aligned.m8n8.x4.shared.b16 {%0,%1,%2,%3}, [%4];"
                 : "=r"(r0), "=r"(r1), "=r"(r2), "=r"(r3) : "r"(addr));
}
__device__ __forceinline__ void mma16816(float* c, const uint32_t* a,
                                         uint32_t b0, uint32_t b1) {
    asm volatile(
        "mma.sync.aligned.m16n8k16.row.col.f32.f16.f16.f32 "
        "{%0,%1,%2,%3}, {%4,%5,%6,%7}, {%8,%9}, {%0,%1,%2,%3};"
        : "+f"(c[0]), "+f"(c[1]), "+f"(c[2]), "+f"(c[3])
        : "r"(a[0]), "r"(a[1]), "r"(a[2]), "r"(a[3]), "r"(b0), "r"(b1));
}
__device__ __forceinline__ void cpa16(uint32_t saddr, const void* gaddr) {
    asm volatile("cp.async.cg.shared.global [%0], [%1], 16;"
                 :: "r"(saddr), "l"(gaddr));
}

// ---------------- CSR build (once per call, side stream) --------------------
__global__ void csr_zero(int* cnt, int n) {
    int i = blockIdx.x * blockDim.x + threadIdx.x;
    if (i < n) cnt[i] = 0;
}
__global__ void csr_hist(const int* __restrict__ row, int* cnt, int E) {
    int e = blockIdx.x * blockDim.x + threadIdx.x;
    if (e < E) atomicAdd(&cnt[row[e]], 1);
}
// single block, 1024 threads, n = 8192 (= 1024*8)
__global__ void csr_scan(const int* __restrict__ cnt, int* __restrict__ off, int n) {
    __shared__ int part[1024];
    const int t = threadIdx.x;
    int local[8];
    int sum = 0;
#pragma unroll
    for (int j = 0; j < 8; j++) {
        local[j] = sum;
        sum += cnt[t * 8 + j];
    }
    part[t] = sum;
    __syncthreads();
    for (int d = 1; d < 1024; d <<= 1) {
        int v = (t >= d) ? part[t - d] : 0;
        __syncthreads();
        part[t] += v;
        __syncthreads();
    }
    int base = (t == 0) ? 0 : part[t - 1];
#pragma unroll
    for (int j = 0; j < 8; j++) off[t * 8 + j] = base + local[j];
    if (t == 1023) off[n] = part[1023];
}
__global__ void csr_scatter(const int* __restrict__ row, const int* __restrict__ off,
                            int* cur, int* __restrict__ perm, int E) {
    int e = blockIdx.x * blockDim.x + threadIdx.x;
    if (e >= E) return;
    int r = row[e];
    int pos = off[r] + atomicAdd(&cur[r], 1);
    perm[pos] = e;
}

// ---------------- HMMA per-layer small GEMMs (LN/relu/concat fused) ---------
#define NG_IHI 0
#define NG_ILO 8192
#define NG_WHI 16384
#define NG_WLO 24576
#define NG_TOT 32768

__global__ void __launch_bounds__(128, 4) ngemm_mma(
    const float* __restrict__ inA, const float* __restrict__ inB, int nxrows,
    const float* __restrict__ lng, const float* __restrict__ lnb,
    const float* __restrict__ bilin, const float* __restrict__ Wrel,
    const float* __restrict__ Wroot, const float* __restrict__ bias,
    __half2* __restrict__ hbhi, __half2* __restrict__ hblo,
    __half2* __restrict__ hhi, float* __restrict__ HW,
    float* __restrict__ agg, int relu, int N, int obase) {
    extern __shared__ __align__(16) char smem[];
    const int tid  = threadIdx.x;
    const int row0 = blockIdx.x * 64;
    const int o    = blockIdx.y + obase;
    const uint32_t sb = smem_u32(smem);

    const float* W = (o == 0) ? bilin : (o < 4) ? Wrel + (size_t)(o - 1) * 4096 : Wroot;
    const int act = (o > 0) ? relu : 0;

    const int r    = tid >> 1;
    const int hlf  = tid & 1;
    const int gr   = row0 + r;
    const float* src = (inB && gr >= nxrows)
                     ? (inB + (size_t)(gr - nxrows) * 64 + hlf * 32)
                     : (inA + (size_t)gr * 64 + hlf * 32);
    float v[32];
#pragma unroll
    for (int i = 0; i < 8; i++) {
        float4 t = *(const float4*)(src + i * 4);
        v[i*4+0] = t.x; v[i*4+1] = t.y; v[i*4+2] = t.z; v[i*4+3] = t.w;
    }
    float wv[32];
#pragma unroll
    for (int it = 0; it < 8; it++) {
        const int q  = tid + it * 128;
        const int k0 = (q >> 6) << 2;
        const int n  = q & 63;
#pragma unroll
        for (int j = 0; j < 4; j++)
            wv[it * 4 + j] = __ldg(W + (k0 + j) * 64 + n);
    }

    {
        if (lng) {
            float s = 0.f, q = 0.f;
#pragma unroll
            for (int i = 0; i < 32; i++) { s += v[i]; q += v[i] * v[i]; }
            s += __shfl_xor_sync(0xffffffffu, s, 1);
            q += __shfl_xor_sync(0xffffffffu, q, 1);
            float mu  = s * (1.f / 64.f);
            float inv = rsqrtf(q * (1.f / 64.f) - mu * mu + 1e-5f);
#pragma unroll
            for (int i = 0; i < 32; i++) {
                int c = hlf * 32 + i;
                v[i] = (v[i] - mu) * inv * lng[c] + lnb[c];
            }
        }
        if (o == 0) {
            __half2* dst = hhi + ((size_t)gr * 64 + hlf * 32) / 2;
#pragma unroll
            for (int i = 0; i < 16; i++)
                dst[i] = __halves2half2(__float2half_rn(v[2*i]),
                                        __float2half_rn(v[2*i+1]));
        } else if (act) {
#pragma unroll
            for (int i = 0; i < 32; i++) v[i] = fmaxf(v[i], 0.f);
        }
        const int r7 = r & 7;
#pragma unroll
        for (int u = 0; u < 4; u++) {
            __half hs[8], ls[8];
#pragma unroll
            for (int j = 0; j < 8; j++) {
                float x = v[u * 8 + j];
                __half h = __float2half_rn(x);
                hs[j] = h;
                ls[j] = __float2half_rn(x - __half2float(h));
            }
            uint32_t unit = (uint32_t)(hlf * 4 + u) ^ (uint32_t)r7;
            uint32_t byte = r * 128 + unit * 16;
            *(uint4*)(smem + NG_IHI + byte) = *(uint4*)hs;
            *(uint4*)(smem + NG_ILO + byte) = *(uint4*)ls;
        }
    }

#pragma unroll
    for (int it = 0; it < 8; it++) {
        const int q  = tid + it * 128;
        const int k0 = (q >> 6) << 2;
        const int n  = q & 63;
        __half hs[4], ls[4];
#pragma unroll
        for (int j = 0; j < 4; j++) {
            float w = wv[it * 4 + j];
            __half h = __float2half_rn(w);
            hs[j] = h;
            ls[j] = __float2half_rn(w - __half2float(h));
        }
        uint32_t unit = (uint32_t)(k0 >> 3) ^ (uint32_t)(n & 7);
        uint32_t byte = n * 128 + unit * 16 + (k0 & 7) * 2;
        *(uint2*)(smem + NG_WHI + byte) = *(uint2*)hs;
        *(uint2*)(smem + NG_WLO + byte) = *(uint2*)ls;
    }
    __syncthreads();

    const int lane = tid & 31;
    const int wid  = tid >> 5;
    const int wm   = wid * 16;
    const int a_row = wm + (lane & 15);
    const int a_r7  = a_row & 7;
    const int au    = lane >> 4;
    const int b_row = (lane & 7) + (((lane >> 4) & 1) << 3);
    const int b_r7  = b_row & 7;
    const int bu    = (lane >> 3) & 1;

    const uint32_t ahib = sb + NG_IHI + a_row * 128;
    const uint32_t alob = sb + NG_ILO + a_row * 128;
    const uint32_t whib = sb + NG_WHI + b_row * 128;
    const uint32_t wlob = sb + NG_WLO + b_row * 128;

    float acc[8][4];
#pragma unroll
    for (int i = 0; i < 8; i++)
#pragma unroll
        for (int j = 0; j < 4; j++) acc[i][j] = 0.f;

#pragma unroll
    for (int kc = 0; kc < 4; kc++) {
        const uint32_t aoff = ((((kc << 1) + au) ^ a_r7) << 4);
        const uint32_t boff = ((((kc << 1) + bu) ^ b_r7) << 4);
        uint32_t Ah[4], Al[4];
        ldm_x4(Ah[0], Ah[1], Ah[2], Ah[3], ahib + aoff);
        ldm_x4(Al[0], Al[1], Al[2], Al[3], alob + aoff);
#pragma unroll
        for (int nt = 0; nt < 4; nt++) {
            uint32_t bh[4], bl[4];
            ldm_x4(bh[0], bh[1], bh[2], bh[3], whib + boff + nt * 16 * 128);
            ldm_x4(bl[0], bl[1], bl[2], bl[3], wlob + boff + nt * 16 * 128);
            float* a0 = acc[2 * nt];
            float* a1 = acc[2 * nt + 1];
            mma16816(a0, Ah, bh[0], bh[1]);
            mma16816(a1, Ah, bh[2], bh[3]);
            mma16816(a0, Al, bh[0], bh[1]);
            mma16816(a1, Al, bh[2], bh[3]);
            mma16816(a0, Ah, bl[0], bl[1]);
            mma16816(a1, Ah, bl[2], bl[3]);
        }
    }

    const int er = lane >> 2;
    const int ec = (lane & 3) * 2;
    const int gro = row0 + wm + er;
    if (o == 0) {
#pragma unroll
        for (int ni = 0; ni < 8; ni++) {
            float* f = acc[ni];
            int col = ni * 8 + ec;
            size_t i0 = ((size_t)gro * 64 + col) / 2;
            size_t i1 = ((size_t)(gro + 8) * 64 + col) / 2;
            __half h0 = __float2half_rn(f[0]), h1 = __float2half_rn(f[1]);
            __half h2 = __float2half_rn(f[2]), h3 = __float2half_rn(f[3]);
            hbhi[i0] = __halves2half2(h0, h1);
            hbhi[i1] = __halves2half2(h2, h3);
            hblo[i0] = __halves2half2(__float2half_rn(f[0] - __half2float(h0)),
                                      __float2half_rn(f[1] - __half2float(h1)));
            hblo[i1] = __halves2half2(__float2half_rn(f[2] - __half2float(h2)),
                                      __float2half_rn(f[3] - __half2float(h3)));
        }
    } else if (o < 4) {
        float* Out = HW + (size_t)(o - 1) * N * 64;
#pragma unroll
        for (int ni = 0; ni < 8; ni++) {
            float* f = acc[ni];
            int col = ni * 8 + ec;
            *(float2*)(Out + (size_t)gro * 64 + col)       = make_float2(f[0], f[1]);
            *(float2*)(Out + (size_t)(gro + 8) * 64 + col) = make_float2(f[2], f[3]);
        }
    } else {
#pragma unroll
        for (int ni = 0; ni < 8; ni++) {
            float* f = acc[ni];
            int col = ni * 8 + ec;
            float b0 = bias[col], b1 = bias[col + 1];
            *(float2*)(agg + (size_t)gro * 64 + col)       = make_float2(f[0] + b0, f[1] + b1);
            *(float2*)(agg + (size_t)(gro + 8) * 64 + col) = make_float2(f[2] + b0, f[3] + b1);
        }
    }
}

// ---------------- persistent HMMA GEMM: C = (Ahi + Alo) @ Bhi^T -------------
#define TILEB 16384
#define SM_TOT (4 * TILEB)

__global__ void __launch_bounds__(256, 2) zgemm_mma(
    const __half* __restrict__ Ahi, const __half* __restrict__ Alo,
    const __half* __restrict__ Bhi, float* __restrict__ C, int N,
    int total_tiles) {
    extern __shared__ __align__(16) char smem[];
    const int tid = threadIdx.x;
    const uint32_t sb = smem_u32(smem);

    const int lrow = tid >> 1;
    const int lcu  = (tid & 1) * 4;
    const int lr7  = lrow & 7;
    const int lcol = (tid & 1) * 32;
    uint32_t soff[4];
#pragma unroll
    for (int i = 0; i < 4; i++)
        soff[i] = lrow * 128 + (((lcu + i) ^ lr7) << 4);

    auto loadA = [&](int band) {
        const __half* gA0 = Ahi + (size_t)(band * 128 + lrow) * 64 + lcol;
        const __half* gA1 = Alo + (size_t)(band * 128 + lrow) * 64 + lcol;
#pragma unroll
        for (int i = 0; i < 4; i++) {
            cpa16(sb + 0 * TILEB + soff[i], gA0 + i * 8);
            cpa16(sb + 1 * TILEB + soff[i], gA1 + i * 8);
        }
    };
    auto issueB = [&](int buf, int n0) {
        const __half* gB = Bhi + (size_t)(n0 * 128 + lrow) * 64 + lcol;
        const uint32_t s0 = sb + 2 * TILEB + buf * TILEB;
#pragma unroll
        for (int i = 0; i < 4; i++)
            cpa16(s0 + soff[i], gB + i * 8);
    };

    const int lane = tid & 31;
    const int wid  = tid >> 5;
    const int wm   = (wid & 3) * 32;
    const int wn   = (wid >> 2) * 64;

    const int a_row = wm + (lane & 15);
    const int a_r7  = a_row & 7;
    const int au    = lane >> 4;
    const int b_row = wn + (lane & 7) + (((lane >> 4) & 1) << 3);
    const int b_r7  = b_row & 7;
    const int bu    = (lane >> 3) & 1;
    const int er = lane >> 2;
    const int ec = (lane & 3) * 2;

    uint32_t aoffk[4], boffk[4];
#pragma unroll
    for (int kc = 0; kc < 4; kc++) {
        aoffk[kc] = ((((kc << 1) + au) ^ a_r7) << 4);
        boffk[kc] = ((((kc << 1) + bu) ^ b_r7) << 4);
    }
    const uint32_t abase_row = sb + a_row * 128;
    const uint32_t bbase0    = sb + 2 * TILEB + b_row * 128;

    const int G = gridDim.x;
    const int p = blockIdx.x;
    const int start = (int)(((long long)p * total_tiles) / G);
    const int end   = (int)(((long long)(p + 1) * total_tiles) / G);
    if (start >= end) return;

    int curBand = start >> 6;
    loadA(curBand);
    issueB(0, start & 63);
    asm volatile("cp.async.commit_group;");

    int idx = 0;
    for (int t = start; t < end; t++, idx++) {
        const int band = t >> 6;
        if (band != curBand) {
            loadA(band);
            asm volatile("cp.async.commit_group;");
            curBand = band;
        }
        const int buf = idx & 1;
        if (t + 1 < end) issueB(1 - buf, (t + 1) & 63);
        asm volatile("cp.async.commit_group;");
        asm volatile("cp.async.wait_group 1;");
        __syncthreads();

        const uint32_t bbase_row = bbase0 + (buf ? (uint32_t)TILEB : 0u);

        float acc[16][4];
#pragma unroll
        for (int i = 0; i < 16; i++)
#pragma unroll
            for (int j = 0; j < 4; j++) acc[i][j] = 0.f;

#pragma unroll
        for (int kc = 0; kc < 4; kc++) {
            uint32_t Ah[8], Al[8], bh[16];
            ldm_x4(Ah[0], Ah[1], Ah[2], Ah[3], abase_row + aoffk[kc]);
            ldm_x4(Ah[4], Ah[5], Ah[6], Ah[7], abase_row + aoffk[kc] + 16 * 128);
            ldm_x4(Al[0], Al[1], Al[2], Al[3], abase_row + TILEB + aoffk[kc]);
            ldm_x4(Al[4], Al[5], Al[6], Al[7], abase_row + TILEB + aoffk[kc] + 16 * 128);
#pragma unroll
            for (int nt2 = 0; nt2 < 4; nt2++)
                ldm_x4(bh[4 * nt2], bh[4 * nt2 + 1], bh[4 * nt2 + 2], bh[4 * nt2 + 3],
                       bbase_row + boffk[kc] + nt2 * 16 * 128);
#pragma unroll
            for (int nt2 = 0; nt2 < 4; nt2++) {
                mma16816(acc[2 * nt2],         Ah,     bh[4 * nt2],     bh[4 * nt2 + 1]);
                mma16816(acc[2 * nt2 + 1],     Ah,     bh[4 * nt2 + 2], bh[4 * nt2 + 3]);
                mma16816(acc[8 + 2 * nt2],     Ah + 4, bh[4 * nt2],     bh[4 * nt2 + 1]);
                mma16816(acc[8 + 2 * nt2 + 1], Ah + 4, bh[4 * nt2 + 2], bh[4 * nt2 + 3]);
            }
#pragma unroll
            for (int nt2 = 0; nt2 < 4; nt2++) {
                mma16816(acc[2 * nt2],         Al,     bh[4 * nt2],     bh[4 * nt2 + 1]);
                mma16816(acc[2 * nt2 + 1],     Al,     bh[4 * nt2 + 2], bh[4 * nt2 + 3]);
                mma16816(acc[8 + 2 * nt2],     Al + 4, bh[4 * nt2],     bh[4 * nt2 + 1]);
                mma16816(acc[8 + 2 * nt2 + 1], Al + 4, bh[4 * nt2 + 2], bh[4 * nt2 + 3]);
            }
        }

        const int m0 = band * 128;
        const int n0 = (t & 63) * 128;
#pragma unroll
        for (int mi = 0; mi < 2; mi++)
#pragma unroll
            for (int ni = 0; ni < 8; ni++) {
                float* f = acc[mi * 8 + ni];
                size_t rr = (size_t)(m0 + wm + mi * 16 + er);
                int col = n0 + wn + ni * 8 + ec;
                *(float2*)(C + rr * N + col)       = make_float2(f[0], f[1]);
                *(float2*)(C + (rr + 8) * N + col) = make_float2(f[2], f[3]);
            }
        __syncthreads();
    }
}

// ---------------- edge aggregation: warp per row, 8-way ILP gather ----------
// agg[r] += sum_{e in row r} HW[etype[e], col[e]] * Z[r, col[e]] * ev[e]
// No atomics: warp owns its row. 8 edges in flight per chunk (MLP~16).
__global__ void edge_csr(const float* __restrict__ Z, const float* __restrict__ HW,
                         const int* __restrict__ col, const int* __restrict__ et,
                         const float* __restrict__ ev, const int* __restrict__ off,
                         const int* __restrict__ perm, float* __restrict__ agg, int N) {
    int w    = (blockIdx.x * blockDim.x + threadIdx.x) >> 5;
    int lane = threadIdx.x & 31;
    if (w >= N) return;
    int s  = off[w];
    int en = off[w + 1];
    if (s == en) return;
    const float* Zr = Z + (size_t)w * N;
    float2 acc = make_float2(0.f, 0.f);
    for (int i = s; i < en; i += 8) {
        int   cj[8], tj[8];
        float aj[8];
#pragma unroll
        for (int j = 0; j < 8; j++) {
            int idx2 = i + j;
            if (idx2 < en) {
                int e = __ldg(perm + idx2);
                cj[j] = __ldg(col + e);
                tj[j] = __ldg(et + e);
                aj[j] = __ldg(ev + e);
            } else {
                cj[j] = -1;
                aj[j] = 0.f;
                tj[j] = 0;
            }
        }
#pragma unroll
        for (int j = 0; j < 8; j++)
            if (cj[j] >= 0) aj[j] *= __ldg(Zr + cj[j]);
#pragma unroll
        for (int j = 0; j < 8; j++) {
            if (cj[j] >= 0) {
                float2 m = ((const float2*)(HW + ((size_t)tj[j] * N + cj[j]) * 64))[lane];
                acc.x += m.x * aj[j];
                acc.y += m.y * aj[j];
            }
        }
    }
    float2* dst = (float2*)(agg + (size_t)w * 64) + lane;
    float2 d = *dst;
    d.x += acc.x; d.y += acc.y;
    *dst = d;
}

// ---------------------------------------------------------------------------
extern "C" void kernel_launch(void* const* d_in, const int* in_sizes, int n_in,
                              void* d_out, int out_size) {
    const float* x       = (const float*)d_in[0];
    const float* emb     = (const float*)d_in[1];
    const float* bilin   = (const float*)d_in[2];
    const float* eval    = (const float*)d_in[3];
    const float* W_root  = (const float*)d_in[4];
    const float* W_rel   = (const float*)d_in[5];
    const float* bias    = (const float*)d_in[6];
    const float* ln_g    = (const float*)d_in[7];
    const float* ln_b    = (const float*)d_in[8];
    const int*   erow    = (const int*)d_in[9];
    const int*   ecol    = (const int*)d_in[10];
    const int*   etype   = (const int*)d_in[11];

    const int NX = in_sizes[0] / D;
    const int NE = in_sizes[1] / D;
    const int N  = NX + NE;
    const int E  = in_sizes[3];

    float* out   = (float*)d_out;
    float* Hout  = out;
    float* Zbase = out + (size_t)N * D;

    float *HW, *aggA, *aggB;
    uint2 *hbhi, *hblo, *hhi;
    int *cnt, *off, *perm;
    cudaGetSymbolAddress((void**)&HW,   g_HW);
    cudaGetSymbolAddress((void**)&aggA, g_aggA);
    cudaGetSymbolAddress((void**)&aggB, g_aggB);
    cudaGetSymbolAddress((void**)&hbhi, g_hbhi);
    cudaGetSymbolAddress((void**)&hblo, g_hblo);
    cudaGetSymbolAddress((void**)&hhi,  g_hhi);
    cudaGetSymbolAddress((void**)&cnt,  g_cnt);
    cudaGetSymbolAddress((void**)&off,  g_off);
    cudaGetSymbolAddress((void**)&perm, g_perm);

    cudaFuncSetAttribute(zgemm_mma, cudaFuncAttributeMaxDynamicSharedMemorySize, SM_TOT);
    cudaFuncSetAttribute(ngemm_mma, cudaFuncAttributeMaxDynamicSharedMemorySize, NG_TOT);

    static cudaStream_t s2 = nullptr;
    static cudaEvent_t evFork = nullptr, evRest = nullptr;
    if (!s2) {
        cudaStreamCreateWithFlags(&s2, cudaStreamNonBlocking);
        cudaEventCreateWithFlags(&evFork, cudaEventDisableTiming);
        cudaEventCreateWithFlags(&evRest, cudaEventDisableTiming);
    }

    int nsm = 148;
    cudaDeviceGetAttribute(&nsm, cudaDevAttrMultiProcessorCount, 0);

    const int tiles_n = N / 128;
    const int total_tiles = tiles_n * tiles_n;
    const int zgrid = 2 * nsm;
    const int edge_blocks = (N * 32 + 255) / 256;

    // CSR build on side stream — hidden under layer-0 ngemm/zgemm; edge(0)
    // waits on evRest which is recorded after these on s2.
    csr_zero<<<(N + 255) / 256, 256, 0, s2>>>(cnt, N);
    csr_hist<<<(E + 255) / 256, 256, 0, s2>>>(erow, cnt, E);
    csr_scan<<<1, 1024, 0, s2>>>(cnt, off, N);
    csr_zero<<<(N + 255) / 256, 256, 0, s2>>>(cnt, N);
    csr_scatter<<<(E + 255) / 256, 256, 0, s2>>>(erow, off, cnt, perm, E);

    const float* insA[3] = { x, aggA, aggB };
    const float* insB[3] = { emb, nullptr, nullptr };
    float*       outs[3] = { aggA, aggB, Hout };

    for (int l = 0; l < 3; l++) {
        float* Zl   = Zbase + (size_t)l * N * N;
        const float* lng = (l == 0) ? nullptr : ln_g + (size_t)(l - 1) * D;
        const float* lnb = (l == 0) ? nullptr : ln_b + (size_t)(l - 1) * D;
        int relu = (l > 0) ? 1 : 0;

        // fork: HW + agg (o=1..4) on s2, overlapping o=0 + zgemm on main
        cudaEventRecord(evFork, 0);
        cudaStreamWaitEvent(s2, evFork, 0);
        ngemm_mma<<<dim3(N / 64, 4), 128, NG_TOT, s2>>>(
            insA[l], insB[l], NX, lng, lnb,
            bilin + (size_t)l * D * D, W_rel + (size_t)l * 3 * D * D,
            W_root + (size_t)l * D * D, bias + (size_t)l * D,
            (__half2*)hbhi, (__half2*)hblo, (__half2*)hhi,
            HW, outs[l], relu, N, /*obase=*/1);
        cudaEventRecord(evRest, s2);

        ngemm_mma<<<dim3(N / 64, 1), 128, NG_TOT>>>(
            insA[l], insB[l], NX, lng, lnb,
            bilin + (size_t)l * D * D, W_rel + (size_t)l * 3 * D * D,
            W_root + (size_t)l * D * D, bias + (size_t)l * D,
            (__half2*)hbhi, (__half2*)hblo, (__half2*)hhi,
            HW, outs[l], relu, N, /*obase=*/0);
        zgemm_mma<<<zgrid, 256, SM_TOT>>>((const __half*)hbhi, (const __half*)hblo,
                                          (const __half*)hhi, Zl, N, total_tiles);

        // join: edge needs Z, HW, agg (and CSR, ordered before rest on s2)
        cudaStreamWaitEvent(0, evRest, 0);
        edge_csr<<<edge_blocks, 256>>>(Zl, HW, ecol, etype, eval, off, perm,
                                       outs[l], N);
    }
}